// round 16
// baseline (speedup 1.0000x reference)
#include <cuda_runtime.h>
#include <cuda_fp16.h>
#include <math.h>

#define N_NODES   100000
#define E_EDGES   3200000
#define F_INF     128
#define HC        128
#define H_HEADS   4
#define C_CH      32
#define G_GRAPHS  64
#define NCLS      10
#define NEG_SLOPE 0.2f

#define SCAN_BLK  256
#define NBLK      ((N_NODES + SCAN_BLK - 1) / SCAN_BLK)   // 391

#define GEMM_BLKS ((N_NODES + 63) / 64)            // 1563
#define EDGE_BLKS ((E_EDGES / 4 + 255) / 256)      // 3125

// ---------------- scratch (device globals; zero-initialized at load) -------
__device__ __align__(16) __half g_h16[(size_t)N_NODES * HC];     // 25.6 MB (half h)
__device__ __align__(16) float2 g_eas[N_NODES * H_HEADS];        // (exp(a_src), exp(0.2 a_src))
__device__ __align__(16) float2 g_ead[N_NODES * H_HEADS];        // (exp(a_dst), exp(0.2 a_dst))
__device__ __align__(16) int    g_cnt[N_NODES];                  // histogram -> cursor (re-zeroed by gather)
__device__ __align__(16) int    g_offs[N_NODES + 1];             // CSR offsets
__device__ __align__(16) int    g_csrc[E_EDGES];                 // src ids grouped by dst (compact)
__device__ __align__(16) float  g_pool[G_GRAPHS * HC];           // pooled sums (re-zeroed by classify)
__device__ __align__(16) unsigned long long g_flag[NBLK];        // lookback flags (re-zeroed by classify)

__device__ __forceinline__ void red_add_v4(float* addr, float a, float b, float c, float d) {
    asm volatile("red.global.add.v4.f32 [%0], {%1,%2,%3,%4};"
                 :: "l"(__cvta_generic_to_global(addr)),
                    "f"(a), "f"(b), "f"(c), "f"(d)
                 : "memory");
}

__device__ __forceinline__ float f2tf32(float x) {
    unsigned u;
    asm("cvt.rna.tf32.f32 %0, %1;" : "=r"(u) : "f"(x));
    return __uint_as_float(u);
}

__device__ __forceinline__ void mma_tf32(float* d,
                                         unsigned a0, unsigned a1, unsigned a2, unsigned a3,
                                         unsigned b0, unsigned b1) {
    asm volatile("mma.sync.aligned.m16n8k8.row.col.f32.tf32.tf32.f32 "
                 "{%0,%1,%2,%3},{%4,%5,%6,%7},{%8,%9},{%0,%1,%2,%3};"
                 : "+f"(d[0]), "+f"(d[1]), "+f"(d[2]), "+f"(d[3])
                 : "r"(a0), "r"(a1), "r"(a2), "r"(a3), "r"(b0), "r"(b1));
}

// ---------------- kernel 0: histogram of dst (g_cnt pre-zeroed) ------------
__global__ void hist_kernel(const int* __restrict__ dst) {
    int i = blockIdx.x * blockDim.x + threadIdx.x;
    if (i < E_EDGES / 4) {
        int4 d4 = ((const int4*)dst)[i];
        atomicAdd(&g_cnt[d4.x], 1);
        atomicAdd(&g_cnt[d4.y], 1);
        atomicAdd(&g_cnt[d4.z], 1);
        atomicAdd(&g_cnt[d4.w], 1);
    }
}

// ---------------- kernel 1: single-pass decoupled-lookback scan ------------
__global__ void scan_lookback() {
    __shared__ int warp_sums[SCAN_BLK / 32];
    __shared__ int s_exc;
    volatile unsigned long long* vf = g_flag;

    const int tid  = threadIdx.x;
    const int lane = tid & 31;
    const int wid  = tid >> 5;
    const int i    = blockIdx.x * SCAN_BLK + tid;

    int v = (i < N_NODES) ? g_cnt[i] : 0;

    int x = v;
#pragma unroll
    for (int o = 1; o < 32; o <<= 1) {
        int y = __shfl_up_sync(0xffffffffu, x, o);
        if (lane >= o) x += y;
    }
    if (lane == 31) warp_sums[wid] = x;
    __syncthreads();
    if (wid == 0) {
        int w = (lane < SCAN_BLK / 32) ? warp_sums[lane] : 0;
#pragma unroll
        for (int o = 1; o < SCAN_BLK / 32; o <<= 1) {
            int y = __shfl_up_sync(0xffffffffu, w, o);
            if (lane >= o) w += y;
        }
        if (lane < SCAN_BLK / 32) warp_sums[lane] = w;
    }
    __syncthreads();

    const int block_total = warp_sums[SCAN_BLK / 32 - 1];
    const int local_exc   = x - v + (wid > 0 ? warp_sums[wid - 1] : 0);

    if (tid == 0) {
        unsigned long long w =
            ((blockIdx.x == 0 ? 2ull : 1ull) << 32) | (unsigned)block_total;
        vf[blockIdx.x] = w;
        __threadfence();
    }
    if (blockIdx.x == 0) {
        if (tid == 0) s_exc = 0;
    } else if (wid == 0) {
        int running = 0;
        int base = blockIdx.x - 1;
        while (true) {
            int idx = base - lane;
            unsigned long long w;
            if (idx < 0) {
                w = (2ull << 32);
            } else {
                do { w = vf[idx]; } while (w == 0ull);
            }
            int st  = (int)(w >> 32);
            int val = (int)(w & 0xffffffffu);
            unsigned pmask = __ballot_sync(0xffffffffu, st == 2);
            if (pmask) {
                int L = __ffs(pmask) - 1;
                int contrib = (lane <= L) ? val : 0;
#pragma unroll
                for (int o = 16; o > 0; o >>= 1) contrib += __shfl_xor_sync(0xffffffffu, contrib, o);
                running += contrib;
                break;
            } else {
                int contrib = val;
#pragma unroll
                for (int o = 16; o > 0; o >>= 1) contrib += __shfl_xor_sync(0xffffffffu, contrib, o);
                running += contrib;
                base -= 32;
            }
        }
        if (lane == 0) {
            s_exc = running;
            vf[blockIdx.x] = (2ull << 32) | (unsigned)(running + block_total);
            __threadfence();
        }
    }
    __syncthreads();

    if (i < N_NODES) {
        int e = s_exc + local_exc;
        g_offs[i] = e;
        g_cnt[i]  = e;
    }
    if (blockIdx.x == 0 && tid == 0) g_offs[N_NODES] = E_EDGES;
}

// ---------------- kernel 2: FUSED [tf32-mma gemm blocks | scatter blocks] --
// gemm: block tile 64x128, 8 warps (4 along M x 2 along N), K chunks of 32.
// scatter: CSR bucket fill using g_cnt cursors (needs scan done).
__global__ void fused_gemm_scatter(const float* __restrict__ x, const float* __restrict__ W,
                                   const float* __restrict__ att_src, const float* __restrict__ att_dst,
                                   const int* __restrict__ src, const int* __restrict__ dst) {
    if (blockIdx.x >= GEMM_BLKS) {
        int i = (blockIdx.x - GEMM_BLKS) * blockDim.x + threadIdx.x;
        if (i < E_EDGES / 4) {
            int4 s4 = ((const int4*)src)[i];
            int4 d4 = ((const int4*)dst)[i];
            g_csrc[atomicAdd(&g_cnt[d4.x], 1)] = s4.x;
            g_csrc[atomicAdd(&g_cnt[d4.y], 1)] = s4.y;
            g_csrc[atomicAdd(&g_cnt[d4.z], 1)] = s4.z;
            g_csrc[atomicAdd(&g_cnt[d4.w], 1)] = s4.w;
        }
        return;
    }

    __shared__ __align__(16) float xs[64][33];     // tf32-rounded x tile
    __shared__ __align__(16) float ws[32][132];    // tf32-rounded W tile
    __shared__ __align__(16) float att_s[2][HC];

    const int tid    = threadIdx.x;
    const int lane   = tid & 31;
    const int warp   = tid >> 5;
    const int warp_m = warp & 3;                   // 0..3 -> rows warp_m*16
    const int warp_n = warp >> 2;                  // 0..1 -> cols warp_n*64
    const int gid    = lane >> 2;                  // 0..7
    const int tig    = lane & 3;                   // 0..3
    const int row0   = blockIdx.x * 64;
    const int cn0    = warp_n * 64;

    if (tid < HC) { att_s[0][tid] = att_src[tid]; att_s[1][tid] = att_dst[tid]; }

    float acc[8][4];
#pragma unroll
    for (int t = 0; t < 8; ++t)
#pragma unroll
        for (int c = 0; c < 4; ++c) acc[t][c] = 0.f;

    for (int kc = 0; kc < 4; ++kc) {
        // stage x chunk (64x32), converting to tf32 bits
#pragma unroll
        for (int i = 0; i < 2; ++i) {
            int idx = tid + i * 256;
            int r = idx >> 3, c4 = idx & 7;
            float4 v = make_float4(0.f, 0.f, 0.f, 0.f);
            if (row0 + r < N_NODES)
                v = *(const float4*)&x[(size_t)(row0 + r) * F_INF + kc * 32 + c4 * 4];
            xs[r][c4 * 4 + 0] = f2tf32(v.x); xs[r][c4 * 4 + 1] = f2tf32(v.y);
            xs[r][c4 * 4 + 2] = f2tf32(v.z); xs[r][c4 * 4 + 3] = f2tf32(v.w);
        }
        // stage W chunk (32x128), converting to tf32 bits
#pragma unroll
        for (int i = 0; i < 4; ++i) {
            int idx = tid + i * 256;
            int r = idx >> 5, c4 = idx & 31;
            float4 v = *(const float4*)&W[(size_t)(kc * 32 + r) * HC + c4 * 4];
            float4 cv = make_float4(f2tf32(v.x), f2tf32(v.y), f2tf32(v.z), f2tf32(v.w));
            *(float4*)&ws[r][c4 * 4] = cv;
        }
        __syncthreads();

#pragma unroll
        for (int ks = 0; ks < 4; ++ks) {
            int k = ks * 8;
            int r0 = warp_m * 16 + gid;
            unsigned a0 = __float_as_uint(xs[r0    ][k + tig    ]);
            unsigned a1 = __float_as_uint(xs[r0 + 8][k + tig    ]);
            unsigned a2 = __float_as_uint(xs[r0    ][k + tig + 4]);
            unsigned a3 = __float_as_uint(xs[r0 + 8][k + tig + 4]);
#pragma unroll
            for (int t = 0; t < 8; ++t) {
                unsigned b0 = __float_as_uint(ws[k + tig    ][cn0 + t * 8 + gid]);
                unsigned b1 = __float_as_uint(ws[k + tig + 4][cn0 + t * 8 + gid]);
                mma_tf32(acc[t], a0, a1, a2, a3, b0, b1);
            }
        }
        __syncthreads();
    }

    // ---------------- epilogue: h (half2) + attention exp tables ----------
    const int r0 = row0 + warp_m * 16 + gid;
    const int r1 = r0 + 8;

    float ps[2][2] = {{0.f,0.f},{0.f,0.f}};   // [rowpart][headbit]
    float pd[2][2] = {{0.f,0.f},{0.f,0.f}};
#pragma unroll
    for (int t = 0; t < 8; ++t) {
        int hb   = t >> 2;
        int col0 = cn0 + t * 8 + 2 * tig;
        float as0 = att_s[0][col0], as1 = att_s[0][col0 + 1];
        float ad0 = att_s[1][col0], ad1 = att_s[1][col0 + 1];
        ps[0][hb] += acc[t][0] * as0 + acc[t][1] * as1;
        ps[1][hb] += acc[t][2] * as0 + acc[t][3] * as1;
        pd[0][hb] += acc[t][0] * ad0 + acc[t][1] * ad1;
        pd[1][hb] += acc[t][2] * ad0 + acc[t][3] * ad1;
        if (r0 < N_NODES)
            *(__half2*)&g_h16[(size_t)r0 * HC + col0] = __floats2half2_rn(acc[t][0], acc[t][1]);
        if (r1 < N_NODES)
            *(__half2*)&g_h16[(size_t)r1 * HC + col0] = __floats2half2_rn(acc[t][2], acc[t][3]);
    }
#pragma unroll
    for (int rp = 0; rp < 2; ++rp)
#pragma unroll
        for (int hb = 0; hb < 2; ++hb) {
#pragma unroll
            for (int o = 1; o < 4; o <<= 1) {
                ps[rp][hb] += __shfl_xor_sync(0xffffffffu, ps[rp][hb], o);
                pd[rp][hb] += __shfl_xor_sync(0xffffffffu, pd[rp][hb], o);
            }
        }
    if (tig == 0) {
#pragma unroll
        for (int rp = 0; rp < 2; ++rp) {
            int row = rp ? r1 : r0;
            if (row < N_NODES) {
#pragma unroll
                for (int hb = 0; hb < 2; ++hb) {
                    int head = warp_n * 2 + hb;
                    g_eas[row * H_HEADS + head] =
                        make_float2(__expf(ps[rp][hb]), __expf(NEG_SLOPE * ps[rp][hb]));
                    g_ead[row * H_HEADS + head] =
                        make_float2(__expf(pd[rp][hb]), __expf(NEG_SLOPE * pd[rp][hb]));
                }
            }
        }
    }
}

// ---------------- kernel 3: gather (R10 structure, unroll 16) --------------
__global__ void gat_gather(const int* __restrict__ batch,
                           const float* __restrict__ conv_bias) {
    const int lane = threadIdx.x & 31;
    const int d = blockIdx.x * 8 + (threadIdx.x >> 5);
    if (d >= N_NODES) return;
    const int head = lane >> 3;

    const int o0 = g_offs[d], o1 = g_offs[d + 1];
    const float2 ead = g_ead[d * H_HEADS + head];

    float4 acc = make_float4(0.f, 0.f, 0.f, 0.f);
    float densum = 0.f;

    int base = o0;
    for (; base + 32 <= o1; base += 32) {
        int eid = g_csrc[base + lane];
#pragma unroll 16
        for (int j = 0; j < 32; ++j) {
            int s = __shfl_sync(0xffffffffu, eid, j);
            float2 ef = __ldg(&g_eas[s * H_HEADS + head]);
            float p = ef.x * ead.x;
            float w = (p > 1.f) ? p : ef.y * ead.y;
            uint2 hh = __ldg(&((const uint2*)g_h16)[(size_t)s * 32 + lane]);
            float2 h01 = __half22float2(*(__half2*)&hh.x);
            float2 h23 = __half22float2(*(__half2*)&hh.y);
            acc.x += w * h01.x; acc.y += w * h01.y;
            acc.z += w * h23.x; acc.w += w * h23.y;
            densum += w;
        }
    }
    int rem = o1 - base;
    if (rem > 0) {
        int eid = (lane < rem) ? g_csrc[base + lane] : 0;
#pragma unroll 4
        for (int j = 0; j < rem; ++j) {
            int s = __shfl_sync(0xffffffffu, eid, j);
            float2 ef = __ldg(&g_eas[s * H_HEADS + head]);
            float p = ef.x * ead.x;
            float w = (p > 1.f) ? p : ef.y * ead.y;
            uint2 hh = __ldg(&((const uint2*)g_h16)[(size_t)s * 32 + lane]);
            float2 h01 = __half22float2(*(__half2*)&hh.x);
            float2 h23 = __half22float2(*(__half2*)&hh.y);
            acc.x += w * h01.x; acc.y += w * h01.y;
            acc.z += w * h23.x; acc.w += w * h23.y;
            densum += w;
        }
    }

    float inv = (densum > 0.f) ? 1.f / densum : 0.f;
    float4 bv = __ldg(&((const float4*)conv_bias)[lane]);
    float vx = acc.x * inv + bv.x; vx = vx > 0.f ? vx : __expf(vx) - 1.f;
    float vy = acc.y * inv + bv.y; vy = vy > 0.f ? vy : __expf(vy) - 1.f;
    float vz = acc.z * inv + bv.z; vz = vz > 0.f ? vz : __expf(vz) - 1.f;
    float vw = acc.w * inv + bv.w; vw = vw > 0.f ? vw : __expf(vw) - 1.f;

    int g = batch[d];
    red_add_v4(&g_pool[g * HC + lane * 4], vx, vy, vz, vw);

    if (lane == 0) g_cnt[d] = 0;          // restore invariant for next replay
}

// ---------------- kernel 4: classifier + log_softmax + state reset ---------
__global__ void classify(const int* __restrict__ batch,
                         const float* __restrict__ lin_w,
                         const float* __restrict__ lin_b,
                         float* __restrict__ out) {
    int g = blockIdx.x, t = threadIdx.x;
    __shared__ float p[HC];
    __shared__ float logits[NCLS];
    __shared__ int s_cnt;
    if (t == 0) {
        int lo = 0, hi = N_NODES;
        while (lo < hi) { int mid = (lo + hi) >> 1; if (batch[mid] <  g) lo = mid + 1; else hi = mid; }
        int lb = lo;
        lo = lb; hi = N_NODES;
        while (lo < hi) { int mid = (lo + hi) >> 1; if (batch[mid] <= g) lo = mid + 1; else hi = mid; }
        s_cnt = lo - lb;
    }
    __syncthreads();
    float cnt = fmaxf((float)s_cnt, 1.0f);
    p[t] = g_pool[g * HC + t] / cnt;
    g_pool[g * HC + t] = 0.f;                       // restore invariant
    if (g == 0) {                                   // clear lookback flags
        for (int i = t; i < NBLK; i += blockDim.x) g_flag[i] = 0ull;
    }
    __syncthreads();
    if (t < NCLS) {
        float acc = lin_b[t];
#pragma unroll 16
        for (int c = 0; c < HC; ++c) acc += p[c] * lin_w[c * NCLS + t];
        logits[t] = acc;
    }
    __syncthreads();
    if (t < NCLS) {
        float m = logits[0];
#pragma unroll
        for (int j = 1; j < NCLS; ++j) m = fmaxf(m, logits[j]);
        float ssum = 0.f;
#pragma unroll
        for (int j = 0; j < NCLS; ++j) ssum += __expf(logits[j] - m);
        out[g * NCLS + t] = logits[t] - m - logf(ssum);
    }
}

// ---------------- launch ----------------------------------------------------
extern "C" void kernel_launch(void* const* d_in, const int* in_sizes, int n_in,
                              void* d_out, int out_size) {
    const float* x        = (const float*)d_in[0];
    const int*   ei       = (const int*)d_in[1];     // int32 (JAX truncates int64)
    const int*   batch    = (const int*)d_in[2];
    const float* W        = (const float*)d_in[3];
    const float* att_src  = (const float*)d_in[4];
    const float* att_dst  = (const float*)d_in[5];
    const float* conv_b   = (const float*)d_in[6];
    const float* lin_w    = (const float*)d_in[7];
    const float* lin_b    = (const float*)d_in[8];
    float*       out      = (float*)d_out;

    const int* src = ei;
    const int* dst = ei + E_EDGES;

    hist_kernel      <<<EDGE_BLKS, 256>>>(dst);                                        // 0
    scan_lookback    <<<NBLK, SCAN_BLK>>>();                                           // 1
    fused_gemm_scatter<<<GEMM_BLKS + EDGE_BLKS, 256>>>(x, W, att_src, att_dst, src, dst); // 2
    gat_gather       <<<(N_NODES + 7) / 8, 256>>>(batch, conv_b);                      // 3 <- profiled
    classify         <<<G_GRAPHS, 128>>>(batch, lin_w, lin_b, out);                    // 4
}

// round 17
// speedup vs baseline: 1.1472x; 1.1472x over previous
#include <cuda_runtime.h>
#include <cuda_fp16.h>
#include <math.h>

#define N_NODES   100000
#define E_EDGES   3200000
#define F_INF     128
#define HC        128
#define H_HEADS   4
#define C_CH      32
#define G_GRAPHS  64
#define NCLS      10
#define NEG_SLOPE 0.2f

#define SCAN_BLK  256
#define NBLK      ((N_NODES + SCAN_BLK - 1) / SCAN_BLK)   // 391

#define GEMM_BLKS ((N_NODES + 63) / 64)            // 1563
#define EDGE_BLKS ((E_EDGES / 4 + 255) / 256)      // 3125

// ---------------- scratch (device globals; zero-initialized at load) -------
__device__ __align__(16) __half g_h16[(size_t)N_NODES * HC];     // 25.6 MB (half h)
__device__ __align__(16) float2 g_eas[N_NODES * H_HEADS];        // (exp(a_src), exp(0.2 a_src))
__device__ __align__(16) float2 g_ead[N_NODES * H_HEADS];        // (exp(a_dst), exp(0.2 a_dst))
__device__ __align__(16) int    g_cnt[N_NODES];                  // histogram -> cursor (re-zeroed by gather)
__device__ __align__(16) int    g_offs[N_NODES + 1];             // CSR offsets
__device__ __align__(16) int    g_csrc[E_EDGES];                 // src ids grouped by dst (compact)
__device__ __align__(16) float  g_pool[G_GRAPHS * HC];           // pooled sums (re-zeroed by classify)
__device__ __align__(16) unsigned long long g_flag[NBLK];        // lookback flags (re-zeroed by classify)

__device__ __forceinline__ void red_add_v4(float* addr, float a, float b, float c, float d) {
    asm volatile("red.global.add.v4.f32 [%0], {%1,%2,%3,%4};"
                 :: "l"(__cvta_generic_to_global(addr)),
                    "f"(a), "f"(b), "f"(c), "f"(d)
                 : "memory");
}

__device__ __forceinline__ float f2tf32(float x) {
    unsigned u;
    asm("cvt.rna.tf32.f32 %0, %1;" : "=r"(u) : "f"(x));
    return __uint_as_float(u);
}

__device__ __forceinline__ void mma_tf32(float* d,
                                         unsigned a0, unsigned a1, unsigned a2, unsigned a3,
                                         unsigned b0, unsigned b1) {
    asm volatile("mma.sync.aligned.m16n8k8.row.col.f32.tf32.tf32.f32 "
                 "{%0,%1,%2,%3},{%4,%5,%6,%7},{%8,%9},{%0,%1,%2,%3};"
                 : "+f"(d[0]), "+f"(d[1]), "+f"(d[2]), "+f"(d[3])
                 : "r"(a0), "r"(a1), "r"(a2), "r"(a3), "r"(b0), "r"(b1));
}

// ---------------- kernel 0: histogram of dst (g_cnt pre-zeroed) ------------
__global__ void hist_kernel(const int* __restrict__ dst) {
    int i = blockIdx.x * blockDim.x + threadIdx.x;
    if (i < E_EDGES / 4) {
        int4 d4 = ((const int4*)dst)[i];
        atomicAdd(&g_cnt[d4.x], 1);
        atomicAdd(&g_cnt[d4.y], 1);
        atomicAdd(&g_cnt[d4.z], 1);
        atomicAdd(&g_cnt[d4.w], 1);
    }
}

// ---------------- kernel 1: single-pass decoupled-lookback scan ------------
__global__ void scan_lookback() {
    __shared__ int warp_sums[SCAN_BLK / 32];
    __shared__ int s_exc;
    volatile unsigned long long* vf = g_flag;

    const int tid  = threadIdx.x;
    const int lane = tid & 31;
    const int wid  = tid >> 5;
    const int i    = blockIdx.x * SCAN_BLK + tid;

    int v = (i < N_NODES) ? g_cnt[i] : 0;

    int x = v;
#pragma unroll
    for (int o = 1; o < 32; o <<= 1) {
        int y = __shfl_up_sync(0xffffffffu, x, o);
        if (lane >= o) x += y;
    }
    if (lane == 31) warp_sums[wid] = x;
    __syncthreads();
    if (wid == 0) {
        int w = (lane < SCAN_BLK / 32) ? warp_sums[lane] : 0;
#pragma unroll
        for (int o = 1; o < SCAN_BLK / 32; o <<= 1) {
            int y = __shfl_up_sync(0xffffffffu, w, o);
            if (lane >= o) w += y;
        }
        if (lane < SCAN_BLK / 32) warp_sums[lane] = w;
    }
    __syncthreads();

    const int block_total = warp_sums[SCAN_BLK / 32 - 1];
    const int local_exc   = x - v + (wid > 0 ? warp_sums[wid - 1] : 0);

    if (tid == 0) {
        unsigned long long w =
            ((blockIdx.x == 0 ? 2ull : 1ull) << 32) | (unsigned)block_total;
        vf[blockIdx.x] = w;
        __threadfence();
    }
    if (blockIdx.x == 0) {
        if (tid == 0) s_exc = 0;
    } else if (wid == 0) {
        int running = 0;
        int base = blockIdx.x - 1;
        while (true) {
            int idx = base - lane;
            unsigned long long w;
            if (idx < 0) {
                w = (2ull << 32);
            } else {
                do { w = vf[idx]; } while (w == 0ull);
            }
            int st  = (int)(w >> 32);
            int val = (int)(w & 0xffffffffu);
            unsigned pmask = __ballot_sync(0xffffffffu, st == 2);
            if (pmask) {
                int L = __ffs(pmask) - 1;
                int contrib = (lane <= L) ? val : 0;
#pragma unroll
                for (int o = 16; o > 0; o >>= 1) contrib += __shfl_xor_sync(0xffffffffu, contrib, o);
                running += contrib;
                break;
            } else {
                int contrib = val;
#pragma unroll
                for (int o = 16; o > 0; o >>= 1) contrib += __shfl_xor_sync(0xffffffffu, contrib, o);
                running += contrib;
                base -= 32;
            }
        }
        if (lane == 0) {
            s_exc = running;
            vf[blockIdx.x] = (2ull << 32) | (unsigned)(running + block_total);
            __threadfence();
        }
    }
    __syncthreads();

    if (i < N_NODES) {
        int e = s_exc + local_exc;
        g_offs[i] = e;
        g_cnt[i]  = e;
    }
    if (blockIdx.x == 0 && tid == 0) g_offs[N_NODES] = E_EDGES;
}

// ---------------- kernel 2: FUSED [tf32-mma gemm blocks | scatter blocks] --
__global__ void fused_gemm_scatter(const float* __restrict__ x, const float* __restrict__ W,
                                   const float* __restrict__ att_src, const float* __restrict__ att_dst,
                                   const int* __restrict__ src, const int* __restrict__ dst) {
    if (blockIdx.x >= GEMM_BLKS) {
        int i = (blockIdx.x - GEMM_BLKS) * blockDim.x + threadIdx.x;
        if (i < E_EDGES / 4) {
            int4 s4 = ((const int4*)src)[i];
            int4 d4 = ((const int4*)dst)[i];
            g_csrc[atomicAdd(&g_cnt[d4.x], 1)] = s4.x;
            g_csrc[atomicAdd(&g_cnt[d4.y], 1)] = s4.y;
            g_csrc[atomicAdd(&g_cnt[d4.z], 1)] = s4.z;
            g_csrc[atomicAdd(&g_cnt[d4.w], 1)] = s4.w;
        }
        return;
    }

    __shared__ __align__(16) float xs[64][33];     // tf32-rounded x tile
    __shared__ __align__(16) float ws[32][132];    // tf32-rounded W tile
    __shared__ __align__(16) float att_s[2][HC];

    const int tid    = threadIdx.x;
    const int lane   = tid & 31;
    const int warp   = tid >> 5;
    const int warp_m = warp & 3;                   // 0..3 -> rows warp_m*16
    const int warp_n = warp >> 2;                  // 0..1 -> cols warp_n*64
    const int gid    = lane >> 2;                  // 0..7
    const int tig    = lane & 3;                   // 0..3
    const int row0   = blockIdx.x * 64;
    const int cn0    = warp_n * 64;

    if (tid < HC) { att_s[0][tid] = att_src[tid]; att_s[1][tid] = att_dst[tid]; }

    float acc[8][4];
#pragma unroll
    for (int t = 0; t < 8; ++t)
#pragma unroll
        for (int c = 0; c < 4; ++c) acc[t][c] = 0.f;

    for (int kc = 0; kc < 4; ++kc) {
#pragma unroll
        for (int i = 0; i < 2; ++i) {
            int idx = tid + i * 256;
            int r = idx >> 3, c4 = idx & 7;
            float4 v = make_float4(0.f, 0.f, 0.f, 0.f);
            if (row0 + r < N_NODES)
                v = *(const float4*)&x[(size_t)(row0 + r) * F_INF + kc * 32 + c4 * 4];
            xs[r][c4 * 4 + 0] = f2tf32(v.x); xs[r][c4 * 4 + 1] = f2tf32(v.y);
            xs[r][c4 * 4 + 2] = f2tf32(v.z); xs[r][c4 * 4 + 3] = f2tf32(v.w);
        }
#pragma unroll
        for (int i = 0; i < 4; ++i) {
            int idx = tid + i * 256;
            int r = idx >> 5, c4 = idx & 31;
            float4 v = *(const float4*)&W[(size_t)(kc * 32 + r) * HC + c4 * 4];
            float4 cv = make_float4(f2tf32(v.x), f2tf32(v.y), f2tf32(v.z), f2tf32(v.w));
            *(float4*)&ws[r][c4 * 4] = cv;
        }
        __syncthreads();

#pragma unroll
        for (int ks = 0; ks < 4; ++ks) {
            int k = ks * 8;
            int r0 = warp_m * 16 + gid;
            unsigned a0 = __float_as_uint(xs[r0    ][k + tig    ]);
            unsigned a1 = __float_as_uint(xs[r0 + 8][k + tig    ]);
            unsigned a2 = __float_as_uint(xs[r0    ][k + tig + 4]);
            unsigned a3 = __float_as_uint(xs[r0 + 8][k + tig + 4]);
#pragma unroll
            for (int t = 0; t < 8; ++t) {
                unsigned b0 = __float_as_uint(ws[k + tig    ][cn0 + t * 8 + gid]);
                unsigned b1 = __float_as_uint(ws[k + tig + 4][cn0 + t * 8 + gid]);
                mma_tf32(acc[t], a0, a1, a2, a3, b0, b1);
            }
        }
        __syncthreads();
    }

    // ---------------- epilogue: h (half2) + attention exp tables ----------
    const int r0 = row0 + warp_m * 16 + gid;
    const int r1 = r0 + 8;

    float ps[2][2] = {{0.f,0.f},{0.f,0.f}};   // [rowpart][headbit]
    float pd[2][2] = {{0.f,0.f},{0.f,0.f}};
#pragma unroll
    for (int t = 0; t < 8; ++t) {
        int hb   = t >> 2;
        int col0 = cn0 + t * 8 + 2 * tig;
        float as0 = att_s[0][col0], as1 = att_s[0][col0 + 1];
        float ad0 = att_s[1][col0], ad1 = att_s[1][col0 + 1];
        ps[0][hb] += acc[t][0] * as0 + acc[t][1] * as1;
        ps[1][hb] += acc[t][2] * as0 + acc[t][3] * as1;
        pd[0][hb] += acc[t][0] * ad0 + acc[t][1] * ad1;
        pd[1][hb] += acc[t][2] * ad0 + acc[t][3] * ad1;
        if (r0 < N_NODES)
            *(__half2*)&g_h16[(size_t)r0 * HC + col0] = __floats2half2_rn(acc[t][0], acc[t][1]);
        if (r1 < N_NODES)
            *(__half2*)&g_h16[(size_t)r1 * HC + col0] = __floats2half2_rn(acc[t][2], acc[t][3]);
    }
#pragma unroll
    for (int rp = 0; rp < 2; ++rp)
#pragma unroll
        for (int hb = 0; hb < 2; ++hb) {
#pragma unroll
            for (int o = 1; o < 4; o <<= 1) {
                ps[rp][hb] += __shfl_xor_sync(0xffffffffu, ps[rp][hb], o);
                pd[rp][hb] += __shfl_xor_sync(0xffffffffu, pd[rp][hb], o);
            }
        }
    if (tig == 0) {
#pragma unroll
        for (int rp = 0; rp < 2; ++rp) {
            int row = rp ? r1 : r0;
            if (row < N_NODES) {
#pragma unroll
                for (int hb = 0; hb < 2; ++hb) {
                    int head = warp_n * 2 + hb;
                    g_eas[row * H_HEADS + head] =
                        make_float2(__expf(ps[rp][hb]), __expf(NEG_SLOPE * ps[rp][hb]));
                    g_ead[row * H_HEADS + head] =
                        make_float2(__expf(pd[rp][hb]), __expf(NEG_SLOPE * pd[rp][hb]));
                }
            }
        }
    }
}

// ---------------- kernel 3: gather (exact R10 loop; 2-warp blocks) ---------
__global__ void gat_gather(const int* __restrict__ batch,
                           const float* __restrict__ conv_bias) {
    const int lane = threadIdx.x & 31;
    const int d = blockIdx.x * 2 + (threadIdx.x >> 5);
    if (d >= N_NODES) return;
    const int head = lane >> 3;

    const int o0 = g_offs[d], o1 = g_offs[d + 1];
    const float2 ead = g_ead[d * H_HEADS + head];

    float4 acc = make_float4(0.f, 0.f, 0.f, 0.f);
    float densum = 0.f;

    int base = o0;
    for (; base + 32 <= o1; base += 32) {
        int eid = g_csrc[base + lane];
#pragma unroll 8
        for (int j = 0; j < 32; ++j) {
            int s = __shfl_sync(0xffffffffu, eid, j);
            float2 ef = __ldg(&g_eas[s * H_HEADS + head]);
            float p = ef.x * ead.x;
            float w = (p > 1.f) ? p : ef.y * ead.y;
            uint2 hh = __ldg(&((const uint2*)g_h16)[(size_t)s * 32 + lane]);
            float2 h01 = __half22float2(*(__half2*)&hh.x);
            float2 h23 = __half22float2(*(__half2*)&hh.y);
            acc.x += w * h01.x; acc.y += w * h01.y;
            acc.z += w * h23.x; acc.w += w * h23.y;
            densum += w;
        }
    }
    int rem = o1 - base;
    if (rem > 0) {
        int eid = (lane < rem) ? g_csrc[base + lane] : 0;
#pragma unroll 4
        for (int j = 0; j < rem; ++j) {
            int s = __shfl_sync(0xffffffffu, eid, j);
            float2 ef = __ldg(&g_eas[s * H_HEADS + head]);
            float p = ef.x * ead.x;
            float w = (p > 1.f) ? p : ef.y * ead.y;
            uint2 hh = __ldg(&((const uint2*)g_h16)[(size_t)s * 32 + lane]);
            float2 h01 = __half22float2(*(__half2*)&hh.x);
            float2 h23 = __half22float2(*(__half2*)&hh.y);
            acc.x += w * h01.x; acc.y += w * h01.y;
            acc.z += w * h23.x; acc.w += w * h23.y;
            densum += w;
        }
    }

    float inv = (densum > 0.f) ? 1.f / densum : 0.f;
    float4 bv = __ldg(&((const float4*)conv_bias)[lane]);
    float vx = acc.x * inv + bv.x; vx = vx > 0.f ? vx : __expf(vx) - 1.f;
    float vy = acc.y * inv + bv.y; vy = vy > 0.f ? vy : __expf(vy) - 1.f;
    float vz = acc.z * inv + bv.z; vz = vz > 0.f ? vz : __expf(vz) - 1.f;
    float vw = acc.w * inv + bv.w; vw = vw > 0.f ? vw : __expf(vw) - 1.f;

    int g = batch[d];
    red_add_v4(&g_pool[g * HC + lane * 4], vx, vy, vz, vw);

    if (lane == 0) g_cnt[d] = 0;          // restore invariant for next replay
}

// ---------------- kernel 4: classifier + log_softmax + state reset ---------
__global__ void classify(const int* __restrict__ batch,
                         const float* __restrict__ lin_w,
                         const float* __restrict__ lin_b,
                         float* __restrict__ out) {
    int g = blockIdx.x, t = threadIdx.x;
    __shared__ float p[HC];
    __shared__ float logits[NCLS];
    __shared__ int s_cnt;
    if (t == 0) {
        int lo = 0, hi = N_NODES;
        while (lo < hi) { int mid = (lo + hi) >> 1; if (batch[mid] <  g) lo = mid + 1; else hi = mid; }
        int lb = lo;
        lo = lb; hi = N_NODES;
        while (lo < hi) { int mid = (lo + hi) >> 1; if (batch[mid] <= g) lo = mid + 1; else hi = mid; }
        s_cnt = lo - lb;
    }
    __syncthreads();
    float cnt = fmaxf((float)s_cnt, 1.0f);
    p[t] = g_pool[g * HC + t] / cnt;
    g_pool[g * HC + t] = 0.f;                       // restore invariant
    if (g == 0) {                                   // clear lookback flags
        for (int i = t; i < NBLK; i += blockDim.x) g_flag[i] = 0ull;
    }
    __syncthreads();
    if (t < NCLS) {
        float acc = lin_b[t];
#pragma unroll 16
        for (int c = 0; c < HC; ++c) acc += p[c] * lin_w[c * NCLS + t];
        logits[t] = acc;
    }
    __syncthreads();
    if (t < NCLS) {
        float m = logits[0];
#pragma unroll
        for (int j = 1; j < NCLS; ++j) m = fmaxf(m, logits[j]);
        float ssum = 0.f;
#pragma unroll
        for (int j = 0; j < NCLS; ++j) ssum += __expf(logits[j] - m);
        out[g * NCLS + t] = logits[t] - m - logf(ssum);
    }
}

// ---------------- launch ----------------------------------------------------
extern "C" void kernel_launch(void* const* d_in, const int* in_sizes, int n_in,
                              void* d_out, int out_size) {
    const float* x        = (const float*)d_in[0];
    const int*   ei       = (const int*)d_in[1];     // int32 (JAX truncates int64)
    const int*   batch    = (const int*)d_in[2];
    const float* W        = (const float*)d_in[3];
    const float* att_src  = (const float*)d_in[4];
    const float* att_dst  = (const float*)d_in[5];
    const float* conv_b   = (const float*)d_in[6];
    const float* lin_w    = (const float*)d_in[7];
    const float* lin_b    = (const float*)d_in[8];
    float*       out      = (float*)d_out;

    const int* src = ei;
    const int* dst = ei + E_EDGES;

    hist_kernel       <<<EDGE_BLKS, 256>>>(dst);                                          // 0
    scan_lookback     <<<NBLK, SCAN_BLK>>>();                                             // 1
    fused_gemm_scatter<<<GEMM_BLKS + EDGE_BLKS, 256>>>(x, W, att_src, att_dst, src, dst); // 2
    gat_gather        <<<(N_NODES + 1) / 2, 64>>>(batch, conv_b);                         // 3 <- profiled
    classify          <<<G_GRAPHS, 128>>>(batch, lin_w, lin_b, out);                      // 4
}